// round 4
// baseline (speedup 1.0000x reference)
#include <cuda_runtime.h>
#include <cstdint>

#define N_NODES 50000
#define N_HEDGES 10000
#define NNZ_INC 400000
#define NNZ_E 80000
#define NNZ_V 400000
#define D 128
#define GR 64

// ---------------- scratch (device globals; no allocation allowed) ----------------
__device__ float g_S1[(size_t)N_HEDGES * D];  // sum invDV[s]*vfeat[s] into hyperedges
__device__ float g_S2[(size_t)N_HEDGES * D];  // sum vout[s] into hyperedges
__device__ float g_A [(size_t)N_HEDGES * D];  // psi1 result per hyperedge
__device__ float g_A2[(size_t)N_HEDGES * D];  // efeat + spmm(emat, A)  -> _efeat
__device__ float g_E2[(size_t)N_HEDGES * D];  // B + scatter(V3)        -> _efeat2
__device__ float g_V1[(size_t)N_NODES * D];   // sum _efeat[dst] into nodes
__device__ float g_V2[(size_t)N_NODES * D];   // sum efeat[dst] into nodes
__device__ float g_V3[(size_t)N_NODES * D];   // spmm(vmat, V2)
__device__ float g_c1[N_HEDGES];              // sum invDV[s] per hyperedge
__device__ float g_deg[N_HEDGES];             // incidence count per hyperedge

// ---------------- helpers ----------------
__device__ __forceinline__ void red_add4(float* addr, float4 v) {
    asm volatile("red.global.add.v4.f32 [%0], {%1,%2,%3,%4};"
                 :: "l"(__cvta_generic_to_global(addr)),
                    "f"(v.x), "f"(v.y), "f"(v.z), "f"(v.w)
                 : "memory");
}

__device__ __forceinline__ float dot4(float acc, float4 wv, float4 xv) {
    return fmaf(wv.x, xv.x, fmaf(wv.y, xv.y, fmaf(wv.z, xv.z, fmaf(wv.w, xv.w, acc))));
}

// ---------------- zero scratch (must run every launch; graph replays) ----------------
__global__ void zero_bufs() {
    size_t tid = (size_t)blockIdx.x * blockDim.x + threadIdx.x;
    size_t stride = (size_t)gridDim.x * blockDim.x;
    const size_t nE4 = (size_t)N_HEDGES * D / 4;
    const size_t nN4 = (size_t)N_NODES * D / 4;
    float4 z = make_float4(0.f, 0.f, 0.f, 0.f);
    float4* s1 = (float4*)g_S1; float4* s2 = (float4*)g_S2;
    float4* v1 = (float4*)g_V1; float4* v2 = (float4*)g_V2; float4* v3 = (float4*)g_V3;
    for (size_t i = tid; i < nN4; i += stride) {
        v1[i] = z; v2[i] = z; v3[i] = z;
        if (i < nE4) { s1[i] = z; s2[i] = z; }
    }
    for (size_t i = tid; i < N_HEDGES; i += stride) { g_c1[i] = 0.f; g_deg[i] = 0.f; }
}

// ---------------- pass 1: fused incidence scatter ----------------
// S1[dst] += invDV[src]*vfeat[src]; V2[src] += efeat[dst]; c1[dst]+=invDV[src]; deg[dst]+=1
__global__ void scatter1_kernel(const float* __restrict__ vfeat,
                                const float* __restrict__ efeat,
                                const float* __restrict__ invDV,
                                const int* __restrict__ src,
                                const int* __restrict__ dst) {
    int w = (blockIdx.x * blockDim.x + threadIdx.x) >> 5;
    int lane = threadIdx.x & 31;
    if (w >= NNZ_INC) return;
    int s = src[w], d = dst[w];
    float idv = invDV[s];
    float4 v = *(const float4*)(vfeat + (size_t)s * D + lane * 4);
    v.x *= idv; v.y *= idv; v.z *= idv; v.w *= idv;
    red_add4(&g_S1[(size_t)d * D + lane * 4], v);
    float4 e = *(const float4*)(efeat + (size_t)d * D + lane * 4);
    red_add4(&g_V2[(size_t)s * D + lane * 4], e);
    if (lane == 0) {
        atomicAdd(&g_c1[d], idv);
        atomicAdd(&g_deg[d], 1.0f);
    }
}

// ---------------- generic row scatter-add: Y[out_idx[i]] += X[in_idx[i]] ----------------
__global__ void scatter_add_kernel(const int* __restrict__ in_idx,
                                   const int* __restrict__ out_idx,
                                   const float* __restrict__ X,
                                   float* __restrict__ Y, int nnz) {
    int w = (blockIdx.x * blockDim.x + threadIdx.x) >> 5;
    int lane = threadIdx.x & 31;
    if (w >= nnz) return;
    int si = in_idx[w], di = out_idx[w];
    float4 v = *(const float4*)(X + (size_t)si * D + lane * 4);
    red_add4(Y + (size_t)di * D + lane * 4, v);
}

// ---------------- COO spmm: Y[rows[i]] += vals[i] * X[cols[i]] ----------------
__global__ void spmm_kernel(const int* __restrict__ rows, const int* __restrict__ cols,
                            const float* __restrict__ vals,
                            const float* __restrict__ X, float* __restrict__ Y, int nnz) {
    int w = (blockIdx.x * blockDim.x + threadIdx.x) >> 5;
    int lane = threadIdx.x & 31;
    if (w >= nnz) return;
    int r = rows[w], c = cols[w];
    float val = vals[w];
    float4 v = *(const float4*)(X + (size_t)c * D + lane * 4);
    v.x *= val; v.y *= val; v.z *= val; v.w *= val;
    red_add4(Y + (size_t)r * D + lane * 4, v);
}

// ---------------- Y = relu(X @ W^T), W [128,128] row-major ----------------
__global__ void gemm_relu_kernel(const float* __restrict__ X, const float* __restrict__ W,
                                 float* __restrict__ Y, int R) {
    extern __shared__ float sh[];
    float* sW = sh;              // 128 x 132 (padded)
    float* sX = sh + 128 * 132;  // 4 rows x 128
    int t = threadIdx.x;  // 0..127, output column
    for (int idx = t; idx < 128 * 128; idx += 128)
        sW[(idx >> 7) * 132 + (idx & 127)] = W[idx];
    __syncthreads();
    int row0 = blockIdx.x * GR;
    for (int rg = 0; rg < GR; rg += 4) {
        __syncthreads();
        for (int i = t; i < 4 * 128; i += 128) {
            int rr = i >> 7, kk = i & 127;
            int row = row0 + rg + rr;
            sX[i] = (row < R) ? X[(size_t)row * D + kk] : 0.f;
        }
        __syncthreads();
        float a0 = 0.f, a1 = 0.f, a2 = 0.f, a3 = 0.f;
        const float* wr = sW + t * 132;
#pragma unroll 8
        for (int k = 0; k < 128; k += 4) {
            float4 wv = *(const float4*)(wr + k);
            float4 x0 = *(const float4*)(sX + k);
            float4 x1 = *(const float4*)(sX + 128 + k);
            float4 x2 = *(const float4*)(sX + 256 + k);
            float4 x3 = *(const float4*)(sX + 384 + k);
            a0 = dot4(a0, wv, x0); a1 = dot4(a1, wv, x1);
            a2 = dot4(a2, wv, x2); a3 = dot4(a3, wv, x3);
        }
        int row = row0 + rg;
        if (row     < R) Y[(size_t)(row    ) * D + t] = fmaxf(a0, 0.f);
        if (row + 1 < R) Y[(size_t)(row + 1) * D + t] = fmaxf(a1, 0.f);
        if (row + 2 < R) Y[(size_t)(row + 2) * D + t] = fmaxf(a2, 0.f);
        if (row + 3 < R) Y[(size_t)(row + 3) * D + t] = fmaxf(a3, 0.f);
    }
}

// ---------------- hyperedge combine with 256-wide psi weight ----------------
// Aout[e] = dot([Xa[e], coef[e]*efeat[e]], W[t,:]) + coef[e]*b[t], then *oscale[e] if given.
// If Acopy: also Acopy[e] = efeat[e].
__global__ void edge_combine_kernel(const float* __restrict__ Xa,
                                    const float* __restrict__ efeat,
                                    const float* __restrict__ coef,
                                    const float* __restrict__ oscale,
                                    const float* __restrict__ W,   // [128, 256]
                                    const float* __restrict__ b,
                                    float* __restrict__ Aout,
                                    float* __restrict__ Acopy) {
    extern __shared__ float sh[];
    float* sW = sh;              // 128 x 260 (padded)
    float* sX = sh + 128 * 260;  // 4 rows x 256
    int t = threadIdx.x;
    for (int idx = t; idx < 128 * 256; idx += 128)
        sW[(idx >> 8) * 260 + (idx & 255)] = W[idx];
    __syncthreads();
    float bt = b[t];
    int row0 = blockIdx.x * GR;
    for (int rg = 0; rg < GR; rg += 4) {
        __syncthreads();
        for (int i = t; i < 4 * 256; i += 128) {
            int rr = i >> 8, kk = i & 255;
            int row = row0 + rg + rr;
            float val = 0.f;
            if (row < N_HEDGES) {
                if (kk < 128) val = Xa[(size_t)row * D + kk];
                else          val = coef[row] * efeat[(size_t)row * D + (kk - 128)];
            }
            sX[i] = val;
        }
        __syncthreads();
        float a0 = 0.f, a1 = 0.f, a2 = 0.f, a3 = 0.f;
        const float* wr = sW + t * 260;
#pragma unroll 8
        for (int k = 0; k < 256; k += 4) {
            float4 wv = *(const float4*)(wr + k);
            float4 x0 = *(const float4*)(sX + k);
            float4 x1 = *(const float4*)(sX + 256 + k);
            float4 x2 = *(const float4*)(sX + 512 + k);
            float4 x3 = *(const float4*)(sX + 768 + k);
            a0 = dot4(a0, wv, x0); a1 = dot4(a1, wv, x1);
            a2 = dot4(a2, wv, x2); a3 = dot4(a3, wv, x3);
        }
#pragma unroll
        for (int rr = 0; rr < 4; rr++) {
            int row = row0 + rg + rr;
            if (row < N_HEDGES) {
                float acc = (rr == 0) ? a0 : (rr == 1) ? a1 : (rr == 2) ? a2 : a3;
                float o = acc + coef[row] * bt;
                if (oscale) o *= oscale[row];
                Aout[(size_t)row * D + t] = o;
                if (Acopy) Acopy[(size_t)row * D + t] = efeat[(size_t)row * D + t];
            }
        }
    }
}

// ---------------- launch ----------------
extern "C" void kernel_launch(void* const* d_in, const int* in_sizes, int n_in,
                              void* d_out, int out_size) {
    const float* vfeat    = (const float*)d_in[0];
    const float* efeat    = (const float*)d_in[1];
    const float* invDV    = (const float*)d_in[2];
    const float* invDE    = (const float*)d_in[3];
    const int*   inc_src  = (const int*)d_in[4];
    const int*   inc_dst  = (const int*)d_in[5];
    const int*   emat_rows = (const int*)d_in[6];
    const int*   emat_cols = (const int*)d_in[7];
    const float* emat_vals = (const float*)d_in[8];
    const int*   vmat_rows = (const int*)d_in[9];
    const int*   vmat_cols = (const int*)d_in[10];
    const float* vmat_vals = (const float*)d_in[11];
    const float* Wv      = (const float*)d_in[12];
    const float* We      = (const float*)d_in[13];
    const float* psi1_W  = (const float*)d_in[14];
    const float* psi1_b  = (const float*)d_in[15];
    const float* psi2_W  = (const float*)d_in[16];
    const float* psi2_b  = (const float*)d_in[17];

    float* out  = (float*)d_out;
    float* vout = out;                          // [N_NODES, 128]
    float* eout = out + (size_t)N_NODES * D;    // [N_HEDGES, 128]

    float *pS1, *pS2, *pA, *pA2, *pE2, *pV1, *pV2, *pV3, *pc1, *pdeg;
    cudaGetSymbolAddress((void**)&pS1, g_S1);
    cudaGetSymbolAddress((void**)&pS2, g_S2);
    cudaGetSymbolAddress((void**)&pA,  g_A);
    cudaGetSymbolAddress((void**)&pA2, g_A2);
    cudaGetSymbolAddress((void**)&pE2, g_E2);
    cudaGetSymbolAddress((void**)&pV1, g_V1);
    cudaGetSymbolAddress((void**)&pV2, g_V2);
    cudaGetSymbolAddress((void**)&pV3, g_V3);
    cudaGetSymbolAddress((void**)&pc1, g_c1);
    cudaGetSymbolAddress((void**)&pdeg, g_deg);

    size_t smem_g = (size_t)(128 * 132 + 4 * 128) * sizeof(float);
    size_t smem_e = (size_t)(128 * 260 + 4 * 256) * sizeof(float);
    cudaFuncSetAttribute(gemm_relu_kernel,   cudaFuncAttributeMaxDynamicSharedMemorySize, (int)smem_g);
    cudaFuncSetAttribute(edge_combine_kernel, cudaFuncAttributeMaxDynamicSharedMemorySize, (int)smem_e);

    const int SC_BLK = 256;
    int inc_blocks  = (NNZ_INC + (SC_BLK / 32) - 1) / (SC_BLK / 32);
    int emat_blocks = (NNZ_E   + (SC_BLK / 32) - 1) / (SC_BLK / 32);
    int vmat_blocks = (NNZ_V   + (SC_BLK / 32) - 1) / (SC_BLK / 32);

    // 0) zero all atomic targets (scratch persists across graph replays)
    zero_bufs<<<2048, 256>>>();
    // 1) fused incidence pass: S1, V2, c1, deg
    scatter1_kernel<<<inc_blocks, SC_BLK>>>(vfeat, efeat, invDV, inc_src, inc_dst);
    // 2) A = S1@W1v^T + c1*(efeat@W1e^T + b1); A2 = efeat
    edge_combine_kernel<<<(N_HEDGES + GR - 1) / GR, 128, smem_e>>>(
        pS1, efeat, pc1, nullptr, psi1_W, psi1_b, pA, pA2);
    // 3) A2 += emat @ A     -> _efeat
    spmm_kernel<<<emat_blocks, SC_BLK>>>(emat_rows, emat_cols, emat_vals, pA, pA2, NNZ_E);
    // 4) V1[src] += A2[dst] -> _vfeat
    scatter_add_kernel<<<inc_blocks, SC_BLK>>>(inc_dst, inc_src, pA2, pV1, NNZ_INC);
    // 5) vout = relu(V1 @ Wv^T)
    gemm_relu_kernel<<<(N_NODES + GR - 1) / GR, 128, smem_g>>>(pV1, Wv, vout, N_NODES);
    // 6) S2[dst] += vout[src]
    scatter_add_kernel<<<inc_blocks, SC_BLK>>>(inc_src, inc_dst, vout, pS2, NNZ_INC);
    // 7) E2 = (S2@W2v^T + deg*(efeat@W2e^T + b2)) * invDE   (= B)
    edge_combine_kernel<<<(N_HEDGES + GR - 1) / GR, 128, smem_e>>>(
        pS2, efeat, pdeg, invDE, psi2_W, psi2_b, pE2, nullptr);
    // 8) V3 = vmat @ V2
    spmm_kernel<<<vmat_blocks, SC_BLK>>>(vmat_rows, vmat_cols, vmat_vals, pV2, pV3, NNZ_V);
    // 9) E2[dst] += V3[src]  -> _efeat2
    scatter_add_kernel<<<inc_blocks, SC_BLK>>>(inc_src, inc_dst, pV3, pE2, NNZ_INC);
    // 10) eout = relu(E2 @ We^T)
    gemm_relu_kernel<<<(N_HEDGES + GR - 1) / GR, 128, smem_g>>>(pE2, We, eout, N_HEDGES);
}

// round 5
// speedup vs baseline: 2.0505x; 2.0505x over previous
#include <cuda_runtime.h>
#include <cstdint>

#define N_NODES 50000
#define N_HEDGES 10000
#define NNZ_INC 400000
#define NNZ_E 80000
#define NNZ_V 400000
#define D 128

// ---------------- scratch (device globals; no allocation allowed) ----------------
__device__ float g_S1[(size_t)N_HEDGES * D];
__device__ float g_S2[(size_t)N_HEDGES * D];
__device__ float g_A [(size_t)N_HEDGES * D];
__device__ float g_A2[(size_t)N_HEDGES * D];
__device__ float g_E2[(size_t)N_HEDGES * D];
__device__ float g_V1[(size_t)N_NODES * D];
__device__ float g_V2[(size_t)N_NODES * D];
__device__ float g_V3[(size_t)N_NODES * D];
__device__ float g_c1[N_HEDGES];
__device__ float g_deg[N_HEDGES];

// CSR scratch
__device__ int g_ecnt[N_HEDGES];  __device__ int g_eoff[N_HEDGES + 1];  __device__ int g_ecur[N_HEDGES];
__device__ int g_ncnt[N_NODES];   __device__ int g_noff[N_NODES + 1];   __device__ int g_ncur[N_NODES];
__device__ int g_vcnt[N_NODES];   __device__ int g_voff[N_NODES + 1];   __device__ int g_vcur[N_NODES];
__device__ int   g_eidx[NNZ_INC];
__device__ int   g_nidx[NNZ_INC];
__device__ int   g_vidx[NNZ_V];
__device__ float g_vval[NNZ_V];

// ---------------- helpers ----------------
__device__ __forceinline__ void red_add4(float* addr, float4 v) {
    asm volatile("red.global.add.v4.f32 [%0], {%1,%2,%3,%4};"
                 :: "l"(__cvta_generic_to_global(addr)),
                    "f"(v.x), "f"(v.y), "f"(v.z), "f"(v.w)
                 : "memory");
}
// packed fp32x2 (Blackwell): 64-bit container holds two f32 lanes
__device__ __forceinline__ double ffma2(double a, double b, double c) {
    double d;
    asm("fma.rn.f32x2 %0, %1, %2, %3;" : "=d"(d) : "d"(a), "d"(b), "d"(c));
    return d;
}
__device__ __forceinline__ double dup2(float v) {
    double d;
    asm("mov.b64 %0, {%1, %1};" : "=d"(d) : "f"(v));
    return d;
}
__device__ __forceinline__ float2 unpk(double d) {
    float2 r;
    asm("mov.b64 {%0, %1}, %2;" : "=f"(r.x), "=f"(r.y) : "d"(d));
    return r;
}

// ---------------- CSR build ----------------
__global__ void zero_cnt_kernel() {
    int i = blockIdx.x * blockDim.x + threadIdx.x;
    int stride = gridDim.x * blockDim.x;
    for (int k = i; k < N_NODES; k += stride) { g_ncnt[k] = 0; g_vcnt[k] = 0; }
    for (int k = i; k < N_HEDGES; k += stride) g_ecnt[k] = 0;
}

__global__ void hist_kernel(const int* __restrict__ src, const int* __restrict__ dst,
                            const int* __restrict__ vrows) {
    int i = blockIdx.x * blockDim.x + threadIdx.x;
    int stride = gridDim.x * blockDim.x;
    for (int k = i; k < NNZ_INC; k += stride) {
        atomicAdd(&g_ecnt[dst[k]], 1);
        atomicAdd(&g_ncnt[src[k]], 1);
        atomicAdd(&g_vcnt[vrows[k]], 1);   // NNZ_V == NNZ_INC
    }
}

__global__ void scan3_kernel() {
    const int* cnt; int* off; int* cur; int n;
    if (blockIdx.x == 0)      { cnt = g_ecnt; off = g_eoff; cur = g_ecur; n = N_HEDGES; }
    else if (blockIdx.x == 1) { cnt = g_ncnt; off = g_noff; cur = g_ncur; n = N_NODES; }
    else                      { cnt = g_vcnt; off = g_voff; cur = g_vcur; n = N_NODES; }
    __shared__ int ssum[1024];
    int t = threadIdx.x;
    int chunk = (n + 1023) >> 10;
    int b = t * chunk;
    int e = min(b + chunk, n);
    int s = 0;
    for (int i = b; i < e; i++) s += cnt[i];
    ssum[t] = s;
    __syncthreads();
    for (int d = 1; d < 1024; d <<= 1) {
        int v = (t >= d) ? ssum[t - d] : 0;
        __syncthreads();
        ssum[t] += v;
        __syncthreads();
    }
    int ex = (t == 0) ? 0 : ssum[t - 1];
    for (int i = b; i < e; i++) { off[i] = ex; cur[i] = ex; ex += cnt[i]; }
    if (t == 1023) off[n] = ssum[1023];
}

__global__ void fill_kernel(const int* __restrict__ src, const int* __restrict__ dst,
                            const int* __restrict__ vrows, const int* __restrict__ vcols,
                            const float* __restrict__ vvals) {
    int i = blockIdx.x * blockDim.x + threadIdx.x;
    int stride = gridDim.x * blockDim.x;
    for (int k = i; k < NNZ_INC; k += stride) {
        int s = src[k], d = dst[k];
        int pe = atomicAdd(&g_ecur[d], 1);
        g_eidx[pe] = s;
        int pn = atomicAdd(&g_ncur[s], 1);
        g_nidx[pn] = d;
        int r = vrows[k];
        int pv = atomicAdd(&g_vcur[r], 1);
        g_vidx[pv] = vcols[k];
        g_vval[pv] = vvals[k];
    }
}

// ---------------- gather kernels (warp per row) ----------------
__global__ void edge_gather1_kernel(const float* __restrict__ vfeat,
                                    const float* __restrict__ invDV) {
    int w = (blockIdx.x * blockDim.x + threadIdx.x) >> 5;
    int lane = threadIdx.x & 31;
    if (w >= N_HEDGES) return;
    int b = g_eoff[w], e = g_eoff[w + 1];
    float4 a0 = make_float4(0.f, 0.f, 0.f, 0.f), a1 = a0;
    float c0 = 0.f, c1s = 0.f;
    int j = b;
    for (; j + 2 <= e; j += 2) {
        int s0 = g_eidx[j], s1 = g_eidx[j + 1];
        float i0 = invDV[s0], i1 = invDV[s1];
        float4 v0 = *(const float4*)(vfeat + (size_t)s0 * D + lane * 4);
        float4 v1 = *(const float4*)(vfeat + (size_t)s1 * D + lane * 4);
        a0.x = fmaf(i0, v0.x, a0.x); a0.y = fmaf(i0, v0.y, a0.y);
        a0.z = fmaf(i0, v0.z, a0.z); a0.w = fmaf(i0, v0.w, a0.w);
        a1.x = fmaf(i1, v1.x, a1.x); a1.y = fmaf(i1, v1.y, a1.y);
        a1.z = fmaf(i1, v1.z, a1.z); a1.w = fmaf(i1, v1.w, a1.w);
        c0 += i0; c1s += i1;
    }
    for (; j < e; j++) {
        int s0 = g_eidx[j];
        float i0 = invDV[s0];
        float4 v0 = *(const float4*)(vfeat + (size_t)s0 * D + lane * 4);
        a0.x = fmaf(i0, v0.x, a0.x); a0.y = fmaf(i0, v0.y, a0.y);
        a0.z = fmaf(i0, v0.z, a0.z); a0.w = fmaf(i0, v0.w, a0.w);
        c0 += i0;
    }
    a0.x += a1.x; a0.y += a1.y; a0.z += a1.z; a0.w += a1.w;
    *(float4*)(g_S1 + (size_t)w * D + lane * 4) = a0;
    if (lane == 0) { g_c1[w] = c0 + c1s; g_deg[w] = (float)(e - b); }
}

// Y[r] = (addTo ? Y[r] : 0) + sum X[idx[j]]
__global__ void gather_sum_kernel(const int* __restrict__ off, const int* __restrict__ idx,
                                  const float* __restrict__ X, float* __restrict__ Y,
                                  int R, int addTo) {
    int w = (blockIdx.x * blockDim.x + threadIdx.x) >> 5;
    int lane = threadIdx.x & 31;
    if (w >= R) return;
    int b = off[w], e = off[w + 1];
    float4 a0 = make_float4(0.f, 0.f, 0.f, 0.f), a1 = a0;
    int j = b;
    for (; j + 2 <= e; j += 2) {
        int s0 = idx[j], s1 = idx[j + 1];
        float4 v0 = *(const float4*)(X + (size_t)s0 * D + lane * 4);
        float4 v1 = *(const float4*)(X + (size_t)s1 * D + lane * 4);
        a0.x += v0.x; a0.y += v0.y; a0.z += v0.z; a0.w += v0.w;
        a1.x += v1.x; a1.y += v1.y; a1.z += v1.z; a1.w += v1.w;
    }
    for (; j < e; j++) {
        int s0 = idx[j];
        float4 v0 = *(const float4*)(X + (size_t)s0 * D + lane * 4);
        a0.x += v0.x; a0.y += v0.y; a0.z += v0.z; a0.w += v0.w;
    }
    a0.x += a1.x; a0.y += a1.y; a0.z += a1.z; a0.w += a1.w;
    float* yp = Y + (size_t)w * D + lane * 4;
    if (addTo) {
        float4 old = *(float4*)yp;
        a0.x += old.x; a0.y += old.y; a0.z += old.z; a0.w += old.w;
    }
    *(float4*)yp = a0;
}

// Y[r] = sum wv[j] * X[idx[j]]
__global__ void gather_wsum_kernel(const int* __restrict__ off, const int* __restrict__ idx,
                                   const float* __restrict__ wv, const float* __restrict__ X,
                                   float* __restrict__ Y, int R) {
    int w = (blockIdx.x * blockDim.x + threadIdx.x) >> 5;
    int lane = threadIdx.x & 31;
    if (w >= R) return;
    int b = off[w], e = off[w + 1];
    float4 a0 = make_float4(0.f, 0.f, 0.f, 0.f), a1 = a0;
    int j = b;
    for (; j + 2 <= e; j += 2) {
        int s0 = idx[j], s1 = idx[j + 1];
        float w0 = wv[j], w1 = wv[j + 1];
        float4 v0 = *(const float4*)(X + (size_t)s0 * D + lane * 4);
        float4 v1 = *(const float4*)(X + (size_t)s1 * D + lane * 4);
        a0.x = fmaf(w0, v0.x, a0.x); a0.y = fmaf(w0, v0.y, a0.y);
        a0.z = fmaf(w0, v0.z, a0.z); a0.w = fmaf(w0, v0.w, a0.w);
        a1.x = fmaf(w1, v1.x, a1.x); a1.y = fmaf(w1, v1.y, a1.y);
        a1.z = fmaf(w1, v1.z, a1.z); a1.w = fmaf(w1, v1.w, a1.w);
    }
    for (; j < e; j++) {
        int s0 = idx[j];
        float w0 = wv[j];
        float4 v0 = *(const float4*)(X + (size_t)s0 * D + lane * 4);
        a0.x = fmaf(w0, v0.x, a0.x); a0.y = fmaf(w0, v0.y, a0.y);
        a0.z = fmaf(w0, v0.z, a0.z); a0.w = fmaf(w0, v0.w, a0.w);
    }
    a0.x += a1.x; a0.y += a1.y; a0.z += a1.z; a0.w += a1.w;
    *(float4*)(Y + (size_t)w * D + lane * 4) = a0;
}

// ---------------- copy: A2 = efeat ----------------
__global__ void copy_kernel(const float* __restrict__ X, float* __restrict__ Y, size_t n4) {
    size_t i = (size_t)blockIdx.x * blockDim.x + threadIdx.x;
    size_t stride = (size_t)gridDim.x * blockDim.x;
    const float4* xs = (const float4*)X;
    float4* ys = (float4*)Y;
    for (size_t k = i; k < n4; k += stride) ys[k] = xs[k];
}

// ---------------- COO spmm (emat only, 80k nnz) ----------------
__global__ void spmm_kernel(const int* __restrict__ rows, const int* __restrict__ cols,
                            const float* __restrict__ vals,
                            const float* __restrict__ X, float* __restrict__ Y, int nnz) {
    int w = (blockIdx.x * blockDim.x + threadIdx.x) >> 5;
    int lane = threadIdx.x & 31;
    if (w >= nnz) return;
    int r = rows[w], c = cols[w];
    float val = vals[w];
    float4 v = *(const float4*)(X + (size_t)c * D + lane * 4);
    v.x *= val; v.y *= val; v.z *= val; v.w *= val;
    red_add4(Y + (size_t)r * D + lane * 4, v);
}

// ---------------- tiled GEMM: Y = act( [X | coef*ef] @ W^T + coef*b ) * oscale ----------------
// W: [128 out-cols][K], row-major. Block: 64 rows x 128 cols, 256 threads (tc 0..31, tr 0..7).
// Each thread: 4 cols (4*tc..), 8 rows (8*tr..) as 4 f32x2 pairs.
#define GEMM_RT 64
template <int K, bool CONCAT>
__global__ void gemm_tiled_kernel(const float* __restrict__ X, const float* __restrict__ ef,
                                  const float* __restrict__ coef, const float* __restrict__ oscale,
                                  const float* __restrict__ W, const float* __restrict__ bias,
                                  float* __restrict__ Y, int R, int do_relu) {
    extern __shared__ float sh[];
    float* sWt = sh;               // [K][132]  (k-major, padded)
    float* sXt = sh + K * 132;     // [K][68]   (k-major, padded)
    const int tid = threadIdx.x;
    const int tc = tid & 31;       // col group
    const int tr = tid >> 5;       // row group
    const int row0 = blockIdx.x * GEMM_RT;

    // load W transposed: sWt[k][col] = W[col][k]
    for (int idx = tid; idx < 128 * K; idx += 256) {
        int col = idx / K, k = idx - col * K;
        sWt[k * 132 + col] = W[idx];
    }
    // load X tile transposed: sXt[k][row]
    constexpr int NQ = K / 4;
    for (int idx = tid; idx < GEMM_RT * NQ; idx += 256) {
        int row = idx / NQ, kq = idx - row * NQ;
        int kk = kq * 4;
        int gr = row0 + row;
        float4 val = make_float4(0.f, 0.f, 0.f, 0.f);
        if (gr < R) {
            if (!CONCAT || kk < 128) {
                val = *(const float4*)(X + (size_t)gr * 128 + kk);
            } else {
                float cf = coef[gr];
                float4 ev = *(const float4*)(ef + (size_t)gr * 128 + (kk - 128));
                val.x = cf * ev.x; val.y = cf * ev.y; val.z = cf * ev.z; val.w = cf * ev.w;
            }
        }
        float* dstp = sXt + (size_t)kk * 68 + row;
        dstp[0]   = val.x;
        dstp[68]  = val.y;
        dstp[136] = val.z;
        dstp[204] = val.w;
    }
    __syncthreads();

    double acc[4][4];
#pragma unroll
    for (int p = 0; p < 4; p++)
#pragma unroll
        for (int c = 0; c < 4; c++) acc[p][c] = 0.0;

    const int c0 = tc * 4;
    const int r0 = tr * 8;
#pragma unroll 8
    for (int k = 0; k < K; k++) {
        float4 wv = *(const float4*)(sWt + k * 132 + c0);
        double2 xd01 = *(const double2*)(sXt + k * 68 + r0);      // rows (0,1),(2,3)
        double2 xd23 = *(const double2*)(sXt + k * 68 + r0 + 4);  // rows (4,5),(6,7)
        double w0 = dup2(wv.x), w1 = dup2(wv.y), w2 = dup2(wv.z), w3 = dup2(wv.w);
        acc[0][0] = ffma2(xd01.x, w0, acc[0][0]);
        acc[0][1] = ffma2(xd01.x, w1, acc[0][1]);
        acc[0][2] = ffma2(xd01.x, w2, acc[0][2]);
        acc[0][3] = ffma2(xd01.x, w3, acc[0][3]);
        acc[1][0] = ffma2(xd01.y, w0, acc[1][0]);
        acc[1][1] = ffma2(xd01.y, w1, acc[1][1]);
        acc[1][2] = ffma2(xd01.y, w2, acc[1][2]);
        acc[1][3] = ffma2(xd01.y, w3, acc[1][3]);
        acc[2][0] = ffma2(xd23.x, w0, acc[2][0]);
        acc[2][1] = ffma2(xd23.x, w1, acc[2][1]);
        acc[2][2] = ffma2(xd23.x, w2, acc[2][2]);
        acc[2][3] = ffma2(xd23.x, w3, acc[2][3]);
        acc[3][0] = ffma2(xd23.y, w0, acc[3][0]);
        acc[3][1] = ffma2(xd23.y, w1, acc[3][1]);
        acc[3][2] = ffma2(xd23.y, w2, acc[3][2]);
        acc[3][3] = ffma2(xd23.y, w3, acc[3][3]);
    }

    float4 bv = make_float4(0.f, 0.f, 0.f, 0.f);
    if (bias) bv = *(const float4*)(bias + c0);
    int row_base = row0 + r0;
#pragma unroll
    for (int p = 0; p < 4; p++) {
        float2 y0 = unpk(acc[p][0]);
        float2 y1 = unpk(acc[p][1]);
        float2 y2 = unpk(acc[p][2]);
        float2 y3 = unpk(acc[p][3]);
#pragma unroll
        for (int h = 0; h < 2; h++) {
            int row = row_base + 2 * p + h;
            if (row >= R) continue;
            float4 o = (h == 0) ? make_float4(y0.x, y1.x, y2.x, y3.x)
                                : make_float4(y0.y, y1.y, y2.y, y3.y);
            if (bias) {
                float cf = coef ? coef[row] : 1.f;
                o.x = fmaf(cf, bv.x, o.x); o.y = fmaf(cf, bv.y, o.y);
                o.z = fmaf(cf, bv.z, o.z); o.w = fmaf(cf, bv.w, o.w);
            }
            if (oscale) {
                float os = oscale[row];
                o.x *= os; o.y *= os; o.z *= os; o.w *= os;
            }
            if (do_relu) {
                o.x = fmaxf(o.x, 0.f); o.y = fmaxf(o.y, 0.f);
                o.z = fmaxf(o.z, 0.f); o.w = fmaxf(o.w, 0.f);
            }
            *(float4*)(Y + (size_t)row * 128 + c0) = o;
        }
    }
}

// ---------------- launch ----------------
extern "C" void kernel_launch(void* const* d_in, const int* in_sizes, int n_in,
                              void* d_out, int out_size) {
    const float* vfeat    = (const float*)d_in[0];
    const float* efeat    = (const float*)d_in[1];
    const float* invDV    = (const float*)d_in[2];
    const float* invDE    = (const float*)d_in[3];
    const int*   inc_src  = (const int*)d_in[4];
    const int*   inc_dst  = (const int*)d_in[5];
    const int*   emat_rows = (const int*)d_in[6];
    const int*   emat_cols = (const int*)d_in[7];
    const float* emat_vals = (const float*)d_in[8];
    const int*   vmat_rows = (const int*)d_in[9];
    const int*   vmat_cols = (const int*)d_in[10];
    const float* vmat_vals = (const float*)d_in[11];
    const float* Wv      = (const float*)d_in[12];
    const float* We      = (const float*)d_in[13];
    const float* psi1_W  = (const float*)d_in[14];
    const float* psi1_b  = (const float*)d_in[15];
    const float* psi2_W  = (const float*)d_in[16];
    const float* psi2_b  = (const float*)d_in[17];

    float* out  = (float*)d_out;
    float* vout = out;                          // [N_NODES, 128]
    float* eout = out + (size_t)N_NODES * D;    // [N_HEDGES, 128]

    float *pS1, *pS2, *pA, *pA2, *pE2, *pV1, *pV2, *pV3, *pc1, *pdeg;
    int *peoff, *peidx, *pnoff, *pnidx, *pvoff, *pvidx;
    float *pvval;
    cudaGetSymbolAddress((void**)&pS1, g_S1);
    cudaGetSymbolAddress((void**)&pS2, g_S2);
    cudaGetSymbolAddress((void**)&pA,  g_A);
    cudaGetSymbolAddress((void**)&pA2, g_A2);
    cudaGetSymbolAddress((void**)&pE2, g_E2);
    cudaGetSymbolAddress((void**)&pV1, g_V1);
    cudaGetSymbolAddress((void**)&pV2, g_V2);
    cudaGetSymbolAddress((void**)&pV3, g_V3);
    cudaGetSymbolAddress((void**)&pc1, g_c1);
    cudaGetSymbolAddress((void**)&pdeg, g_deg);
    cudaGetSymbolAddress((void**)&peoff, g_eoff);
    cudaGetSymbolAddress((void**)&peidx, g_eidx);
    cudaGetSymbolAddress((void**)&pnoff, g_noff);
    cudaGetSymbolAddress((void**)&pnidx, g_nidx);
    cudaGetSymbolAddress((void**)&pvoff, g_voff);
    cudaGetSymbolAddress((void**)&pvidx, g_vidx);
    cudaGetSymbolAddress((void**)&pvval, g_vval);

    size_t smem128 = (size_t)(128 * 132 + 128 * 68) * sizeof(float);  // 102400
    size_t smem256 = (size_t)(256 * 132 + 256 * 68) * sizeof(float);  // 204800
    cudaFuncSetAttribute(gemm_tiled_kernel<128, false>,
                         cudaFuncAttributeMaxDynamicSharedMemorySize, (int)smem128);
    cudaFuncSetAttribute(gemm_tiled_kernel<256, true>,
                         cudaFuncAttributeMaxDynamicSharedMemorySize, (int)smem256);

    const int BLK = 256;
    int ew = (N_HEDGES + 7) / 8;     // warps-per-block = 8
    int nw = (N_NODES + 7) / 8;
    int gemmN = (N_NODES + GEMM_RT - 1) / GEMM_RT;
    int gemmE = (N_HEDGES + GEMM_RT - 1) / GEMM_RT;
    int emat_blocks = (NNZ_E + 7) / 8;

    // --- CSR build ---
    zero_cnt_kernel<<<256, 256>>>();
    hist_kernel<<<1024, 256>>>(inc_src, inc_dst, vmat_rows);
    scan3_kernel<<<3, 1024>>>();
    fill_kernel<<<1024, 256>>>(inc_src, inc_dst, vmat_rows, vmat_cols, vmat_vals);

    // --- pass 1 ---
    edge_gather1_kernel<<<ew, BLK>>>(vfeat, invDV);                         // S1, c1, deg
    gather_sum_kernel<<<nw, BLK>>>(pnoff, pnidx, efeat, pV2, N_NODES, 0);   // V2
    gemm_tiled_kernel<256, true><<<gemmE, 256, smem256>>>(
        pS1, efeat, pc1, nullptr, psi1_W, psi1_b, pA, N_HEDGES, 0);         // A
    copy_kernel<<<512, 256>>>(efeat, pA2, (size_t)N_HEDGES * D / 4);        // A2 = efeat
    spmm_kernel<<<emat_blocks, BLK>>>(emat_rows, emat_cols, emat_vals, pA, pA2, NNZ_E);
    gather_sum_kernel<<<nw, BLK>>>(pnoff, pnidx, pA2, pV1, N_NODES, 0);     // V1
    gemm_tiled_kernel<128, false><<<gemmN, 256, smem128>>>(
        pV1, nullptr, nullptr, nullptr, Wv, nullptr, vout, N_NODES, 1);     // vout

    // --- pass 2 ---
    gather_sum_kernel<<<ew, BLK>>>(peoff, peidx, vout, pS2, N_HEDGES, 0);   // S2
    gemm_tiled_kernel<256, true><<<gemmE, 256, smem256>>>(
        pS2, efeat, pdeg, invDE, psi2_W, psi2_b, pE2, N_HEDGES, 0);         // E2 = B
    gather_wsum_kernel<<<nw, BLK>>>(pvoff, pvidx, pvval, pV2, pV3, N_NODES);// V3
    gather_sum_kernel<<<ew, BLK>>>(peoff, peidx, pV3, pE2, N_HEDGES, 1);    // E2 += gather
    gemm_tiled_kernel<128, false><<<gemmE, 256, smem128>>>(
        pE2, nullptr, nullptr, nullptr, We, nullptr, eout, N_HEDGES, 1);    // eout
}

// round 6
// speedup vs baseline: 2.1362x; 1.0418x over previous
#include <cuda_runtime.h>
#include <cstdint>

#define N_NODES 50000
#define N_HEDGES 10000
#define NNZ_INC 400000
#define NNZ_E 80000
#define NNZ_V 400000
#define D 128

// ---------------- scratch (device globals; no allocation allowed) ----------------
__device__ float g_S1[(size_t)N_HEDGES * D];
__device__ float g_S2[(size_t)N_HEDGES * D];
__device__ float g_A [(size_t)N_HEDGES * D];
__device__ float g_C [(size_t)N_HEDGES * D];   // emat @ A
__device__ float g_E2[(size_t)N_HEDGES * D];
__device__ float g_GE[(size_t)N_HEDGES * D];   // gather of V3 into edges
__device__ float g_V1[(size_t)N_NODES * D];
__device__ float g_V2[(size_t)N_NODES * D];
__device__ float g_V3[(size_t)N_NODES * D];
__device__ float g_c1[N_HEDGES];
__device__ float g_deg[N_HEDGES];

// CSR scratch (4 CSRs: edge<-inc, node<-inc, node<-vmat, edge<-emat)
__device__ int g_ecnt[N_HEDGES];  __device__ int g_eoff[N_HEDGES + 1];  __device__ int g_ecur[N_HEDGES];
__device__ int g_ncnt[N_NODES];   __device__ int g_noff[N_NODES + 1];   __device__ int g_ncur[N_NODES];
__device__ int g_vcnt[N_NODES];   __device__ int g_voff[N_NODES + 1];   __device__ int g_vcur[N_NODES];
__device__ int g_mcnt[N_HEDGES];  __device__ int g_moff[N_HEDGES + 1];  __device__ int g_mcur[N_HEDGES];
__device__ int   g_eidx[NNZ_INC];
__device__ int   g_nidx[NNZ_INC];
__device__ int   g_vidx[NNZ_V];
__device__ float g_vval[NNZ_V];
__device__ int   g_midx[NNZ_E];
__device__ float g_mval[NNZ_E];

// ---------------- helpers ----------------
__device__ __forceinline__ double ffma2(double a, double b, double c) {
    double d;
    asm("fma.rn.f32x2 %0, %1, %2, %3;" : "=d"(d) : "d"(a), "d"(b), "d"(c));
    return d;
}
__device__ __forceinline__ double dup2(float v) {
    double d;
    asm("mov.b64 %0, {%1, %1};" : "=d"(d) : "f"(v));
    return d;
}
__device__ __forceinline__ float2 unpk(double d) {
    float2 r;
    asm("mov.b64 {%0, %1}, %2;" : "=f"(r.x), "=f"(r.y) : "d"(d));
    return r;
}

// ---------------- CSR build ----------------
__global__ void zero_cnt_kernel() {
    int i = blockIdx.x * blockDim.x + threadIdx.x;
    int stride = gridDim.x * blockDim.x;
    for (int k = i; k < N_NODES; k += stride) { g_ncnt[k] = 0; g_vcnt[k] = 0; }
    for (int k = i; k < N_HEDGES; k += stride) { g_ecnt[k] = 0; g_mcnt[k] = 0; }
}

__global__ void hist_kernel(const int* __restrict__ src, const int* __restrict__ dst,
                            const int* __restrict__ vrows, const int* __restrict__ mrows) {
    int k = blockIdx.x * blockDim.x + threadIdx.x;
    if (k < NNZ_INC) {
        atomicAdd(&g_ecnt[__ldg(dst + k)], 1);
        atomicAdd(&g_ncnt[__ldg(src + k)], 1);
        atomicAdd(&g_vcnt[__ldg(vrows + k)], 1);
        if (k < NNZ_E) atomicAdd(&g_mcnt[__ldg(mrows + k)], 1);
    }
}

__global__ void scan4_kernel() {
    const int* cnt; int* off; int* cur; int n;
    if (blockIdx.x == 0)      { cnt = g_ecnt; off = g_eoff; cur = g_ecur; n = N_HEDGES; }
    else if (blockIdx.x == 1) { cnt = g_ncnt; off = g_noff; cur = g_ncur; n = N_NODES; }
    else if (blockIdx.x == 2) { cnt = g_vcnt; off = g_voff; cur = g_vcur; n = N_NODES; }
    else                      { cnt = g_mcnt; off = g_moff; cur = g_mcur; n = N_HEDGES; }
    __shared__ int ssum[1024];
    int t = threadIdx.x;
    int chunk = (n + 1023) >> 10;
    int b = t * chunk;
    int e = min(b + chunk, n);
    int s = 0;
    for (int i = b; i < e; i++) s += cnt[i];
    ssum[t] = s;
    __syncthreads();
    for (int d = 1; d < 1024; d <<= 1) {
        int v = (t >= d) ? ssum[t - d] : 0;
        __syncthreads();
        ssum[t] += v;
        __syncthreads();
    }
    int ex = (t == 0) ? 0 : ssum[t - 1];
    for (int i = b; i < e; i++) { off[i] = ex; cur[i] = ex; ex += cnt[i]; }
    if (t == 1023) off[n] = ssum[1023];
}

__global__ void fill_kernel(const int* __restrict__ src, const int* __restrict__ dst,
                            const int* __restrict__ vrows, const int* __restrict__ vcols,
                            const float* __restrict__ vvals,
                            const int* __restrict__ mrows, const int* __restrict__ mcols,
                            const float* __restrict__ mvals) {
    int k = blockIdx.x * blockDim.x + threadIdx.x;
    if (k >= NNZ_INC) return;
    int s = __ldg(src + k), d = __ldg(dst + k), r = __ldg(vrows + k);
    int pe = atomicAdd(&g_ecur[d], 1);
    int pn = atomicAdd(&g_ncur[s], 1);
    int pv = atomicAdd(&g_vcur[r], 1);
    g_eidx[pe] = s;
    g_nidx[pn] = d;
    g_vidx[pv] = __ldg(vcols + k);
    g_vval[pv] = __ldg(vvals + k);
    if (k < NNZ_E) {
        int mr = __ldg(mrows + k);
        int pm = atomicAdd(&g_mcur[mr], 1);
        g_midx[pm] = __ldg(mcols + k);
        g_mval[pm] = __ldg(mvals + k);
    }
}

// ---------------- gather kernels (warp per row) ----------------
// S1[e] = sum invDV[s]*vfeat[s]; c1[e] = sum invDV[s]; deg[e] = count
__global__ void edge_gather1_kernel(const float* __restrict__ vfeat,
                                    const float* __restrict__ invDV) {
    int w = (blockIdx.x * blockDim.x + threadIdx.x) >> 5;
    int lane = threadIdx.x & 31;
    if (w >= N_HEDGES) return;
    int b = g_eoff[w], e = g_eoff[w + 1];
    float4 a0 = make_float4(0.f, 0.f, 0.f, 0.f), a1 = a0;
    float c0 = 0.f, c1s = 0.f;
    int j = b;
    for (; j + 2 <= e; j += 2) {
        int s0 = g_eidx[j], s1 = g_eidx[j + 1];
        float i0 = invDV[s0], i1 = invDV[s1];
        float4 v0 = *(const float4*)(vfeat + (size_t)s0 * D + lane * 4);
        float4 v1 = *(const float4*)(vfeat + (size_t)s1 * D + lane * 4);
        a0.x = fmaf(i0, v0.x, a0.x); a0.y = fmaf(i0, v0.y, a0.y);
        a0.z = fmaf(i0, v0.z, a0.z); a0.w = fmaf(i0, v0.w, a0.w);
        a1.x = fmaf(i1, v1.x, a1.x); a1.y = fmaf(i1, v1.y, a1.y);
        a1.z = fmaf(i1, v1.z, a1.z); a1.w = fmaf(i1, v1.w, a1.w);
        c0 += i0; c1s += i1;
    }
    for (; j < e; j++) {
        int s0 = g_eidx[j];
        float i0 = invDV[s0];
        float4 v0 = *(const float4*)(vfeat + (size_t)s0 * D + lane * 4);
        a0.x = fmaf(i0, v0.x, a0.x); a0.y = fmaf(i0, v0.y, a0.y);
        a0.z = fmaf(i0, v0.z, a0.z); a0.w = fmaf(i0, v0.w, a0.w);
        c0 += i0;
    }
    a0.x += a1.x; a0.y += a1.y; a0.z += a1.z; a0.w += a1.w;
    *(float4*)(g_S1 + (size_t)w * D + lane * 4) = a0;
    if (lane == 0) { g_c1[w] = c0 + c1s; g_deg[w] = (float)(e - b); }
}

// Dual gather: YA[r] = sum XA[idx[j]], YB[r] = (sum XA) + sum XB[idx[j]]  (combine=1)
//          or: YA[r] = sum XA[idx[j]], YB[r] = sum XB[idx[j]]            (combine=0)
__global__ void gather_dual_kernel(const int* __restrict__ off, const int* __restrict__ idx,
                                   const float* __restrict__ XA, const float* __restrict__ XB,
                                   float* __restrict__ YA, float* __restrict__ YB,
                                   int R, int combine) {
    int w = (blockIdx.x * blockDim.x + threadIdx.x) >> 5;
    int lane = threadIdx.x & 31;
    if (w >= R) return;
    int b = off[w], e = off[w + 1];
    float4 aa = make_float4(0.f, 0.f, 0.f, 0.f), ab = aa;
    for (int j = b; j < e; j++) {
        int s = idx[j];
        const float* pa = XA + (size_t)s * D + lane * 4;
        const float* pb = XB + (size_t)s * D + lane * 4;
        float4 va = *(const float4*)pa;
        float4 vb = *(const float4*)pb;
        aa.x += va.x; aa.y += va.y; aa.z += va.z; aa.w += va.w;
        ab.x += vb.x; ab.y += vb.y; ab.z += vb.z; ab.w += vb.w;
    }
    *(float4*)(YA + (size_t)w * D + lane * 4) = aa;
    if (combine) {
        ab.x += aa.x; ab.y += aa.y; ab.z += aa.z; ab.w += aa.w;
    }
    *(float4*)(YB + (size_t)w * D + lane * 4) = ab;
}

// Y[r] = sum wv[j] * X[idx[j]]   (weighted CSR gather)
__global__ void gather_wsum_kernel(const int* __restrict__ off, const int* __restrict__ idx,
                                   const float* __restrict__ wv, const float* __restrict__ X,
                                   float* __restrict__ Y, int R) {
    int w = (blockIdx.x * blockDim.x + threadIdx.x) >> 5;
    int lane = threadIdx.x & 31;
    if (w >= R) return;
    int b = off[w], e = off[w + 1];
    float4 a0 = make_float4(0.f, 0.f, 0.f, 0.f), a1 = a0;
    int j = b;
    for (; j + 2 <= e; j += 2) {
        int s0 = idx[j], s1 = idx[j + 1];
        float w0 = wv[j], w1 = wv[j + 1];
        float4 v0 = *(const float4*)(X + (size_t)s0 * D + lane * 4);
        float4 v1 = *(const float4*)(X + (size_t)s1 * D + lane * 4);
        a0.x = fmaf(w0, v0.x, a0.x); a0.y = fmaf(w0, v0.y, a0.y);
        a0.z = fmaf(w0, v0.z, a0.z); a0.w = fmaf(w0, v0.w, a0.w);
        a1.x = fmaf(w1, v1.x, a1.x); a1.y = fmaf(w1, v1.y, a1.y);
        a1.z = fmaf(w1, v1.z, a1.z); a1.w = fmaf(w1, v1.w, a1.w);
    }
    for (; j < e; j++) {
        int s0 = idx[j];
        float w0 = wv[j];
        float4 v0 = *(const float4*)(X + (size_t)s0 * D + lane * 4);
        a0.x = fmaf(w0, v0.x, a0.x); a0.y = fmaf(w0, v0.y, a0.y);
        a0.z = fmaf(w0, v0.z, a0.z); a0.w = fmaf(w0, v0.w, a0.w);
    }
    a0.x += a1.x; a0.y += a1.y; a0.z += a1.z; a0.w += a1.w;
    *(float4*)(Y + (size_t)w * D + lane * 4) = a0;
}

// ---------------- tiled GEMM ----------------
// Y = act( ([X | coef*ef] @ W^T + coef*b) * oscale + addend )
// W: [128 out][K] row-major. Block: 64 rows x 128 cols, 256 threads.
#define GEMM_RT 64
template <int K, bool CONCAT>
__global__ void gemm_tiled_kernel(const float* __restrict__ X, const float* __restrict__ ef,
                                  const float* __restrict__ coef, const float* __restrict__ oscale,
                                  const float* __restrict__ addend,
                                  const float* __restrict__ W, const float* __restrict__ bias,
                                  float* __restrict__ Y, int R, int do_relu) {
    extern __shared__ float sh[];
    float* sWt = sh;               // [K][132]
    float* sXt = sh + K * 132;     // [K][68]
    const int tid = threadIdx.x;
    const int tc = tid & 31;
    const int tr = tid >> 5;
    const int row0 = blockIdx.x * GEMM_RT;

    for (int idx = tid; idx < 128 * K; idx += 256) {
        int col = idx / K, k = idx - col * K;
        sWt[k * 132 + col] = W[idx];
    }
    constexpr int NQ = K / 4;
    for (int idx = tid; idx < GEMM_RT * NQ; idx += 256) {
        int row = idx / NQ, kq = idx - row * NQ;
        int kk = kq * 4;
        int gr = row0 + row;
        float4 val = make_float4(0.f, 0.f, 0.f, 0.f);
        if (gr < R) {
            if (!CONCAT || kk < 128) {
                val = *(const float4*)(X + (size_t)gr * 128 + kk);
            } else {
                float cf = coef[gr];
                float4 ev = *(const float4*)(ef + (size_t)gr * 128 + (kk - 128));
                val.x = cf * ev.x; val.y = cf * ev.y; val.z = cf * ev.z; val.w = cf * ev.w;
            }
        }
        float* dstp = sXt + (size_t)kk * 68 + row;
        dstp[0]   = val.x;
        dstp[68]  = val.y;
        dstp[136] = val.z;
        dstp[204] = val.w;
    }
    __syncthreads();

    double acc[4][4];
#pragma unroll
    for (int p = 0; p < 4; p++)
#pragma unroll
        for (int c = 0; c < 4; c++) acc[p][c] = 0.0;

    const int c0 = tc * 4;
    const int r0 = tr * 8;
#pragma unroll 8
    for (int k = 0; k < K; k++) {
        float4 wv = *(const float4*)(sWt + k * 132 + c0);
        double2 xd01 = *(const double2*)(sXt + k * 68 + r0);
        double2 xd23 = *(const double2*)(sXt + k * 68 + r0 + 4);
        double w0 = dup2(wv.x), w1 = dup2(wv.y), w2 = dup2(wv.z), w3 = dup2(wv.w);
        acc[0][0] = ffma2(xd01.x, w0, acc[0][0]);
        acc[0][1] = ffma2(xd01.x, w1, acc[0][1]);
        acc[0][2] = ffma2(xd01.x, w2, acc[0][2]);
        acc[0][3] = ffma2(xd01.x, w3, acc[0][3]);
        acc[1][0] = ffma2(xd01.y, w0, acc[1][0]);
        acc[1][1] = ffma2(xd01.y, w1, acc[1][1]);
        acc[1][2] = ffma2(xd01.y, w2, acc[1][2]);
        acc[1][3] = ffma2(xd01.y, w3, acc[1][3]);
        acc[2][0] = ffma2(xd23.x, w0, acc[2][0]);
        acc[2][1] = ffma2(xd23.x, w1, acc[2][1]);
        acc[2][2] = ffma2(xd23.x, w2, acc[2][2]);
        acc[2][3] = ffma2(xd23.x, w3, acc[2][3]);
        acc[3][0] = ffma2(xd23.y, w0, acc[3][0]);
        acc[3][1] = ffma2(xd23.y, w1, acc[3][1]);
        acc[3][2] = ffma2(xd23.y, w2, acc[3][2]);
        acc[3][3] = ffma2(xd23.y, w3, acc[3][3]);
    }

    float4 bv = make_float4(0.f, 0.f, 0.f, 0.f);
    if (bias) bv = *(const float4*)(bias + c0);
    int row_base = row0 + r0;
#pragma unroll
    for (int p = 0; p < 4; p++) {
        float2 y0 = unpk(acc[p][0]);
        float2 y1 = unpk(acc[p][1]);
        float2 y2 = unpk(acc[p][2]);
        float2 y3 = unpk(acc[p][3]);
#pragma unroll
        for (int h = 0; h < 2; h++) {
            int row = row_base + 2 * p + h;
            if (row >= R) continue;
            float4 o = (h == 0) ? make_float4(y0.x, y1.x, y2.x, y3.x)
                                : make_float4(y0.y, y1.y, y2.y, y3.y);
            if (bias) {
                float cf = coef ? coef[row] : 1.f;
                o.x = fmaf(cf, bv.x, o.x); o.y = fmaf(cf, bv.y, o.y);
                o.z = fmaf(cf, bv.z, o.z); o.w = fmaf(cf, bv.w, o.w);
            }
            if (oscale) {
                float os = oscale[row];
                o.x *= os; o.y *= os; o.z *= os; o.w *= os;
            }
            if (addend) {
                float4 ad = *(const float4*)(addend + (size_t)row * 128 + c0);
                o.x += ad.x; o.y += ad.y; o.z += ad.z; o.w += ad.w;
            }
            if (do_relu) {
                o.x = fmaxf(o.x, 0.f); o.y = fmaxf(o.y, 0.f);
                o.z = fmaxf(o.z, 0.f); o.w = fmaxf(o.w, 0.f);
            }
            *(float4*)(Y + (size_t)row * 128 + c0) = o;
        }
    }
}

// ---------------- launch ----------------
extern "C" void kernel_launch(void* const* d_in, const int* in_sizes, int n_in,
                              void* d_out, int out_size) {
    const float* vfeat    = (const float*)d_in[0];
    const float* efeat    = (const float*)d_in[1];
    const float* invDV    = (const float*)d_in[2];
    const float* invDE    = (const float*)d_in[3];
    const int*   inc_src  = (const int*)d_in[4];
    const int*   inc_dst  = (const int*)d_in[5];
    const int*   emat_rows = (const int*)d_in[6];
    const int*   emat_cols = (const int*)d_in[7];
    const float* emat_vals = (const float*)d_in[8];
    const int*   vmat_rows = (const int*)d_in[9];
    const int*   vmat_cols = (const int*)d_in[10];
    const float* vmat_vals = (const float*)d_in[11];
    const float* Wv      = (const float*)d_in[12];
    const float* We      = (const float*)d_in[13];
    const float* psi1_W  = (const float*)d_in[14];
    const float* psi1_b  = (const float*)d_in[15];
    const float* psi2_W  = (const float*)d_in[16];
    const float* psi2_b  = (const float*)d_in[17];

    float* out  = (float*)d_out;
    float* vout = out;
    float* eout = out + (size_t)N_NODES * D;

    float *pS1, *pS2, *pA, *pC, *pE2, *pGE, *pV1, *pV2, *pV3, *pc1, *pdeg;
    int *peoff, *peidx, *pnoff, *pnidx, *pvoff, *pvidx, *pmoff, *pmidx;
    float *pvval, *pmval;
    cudaGetSymbolAddress((void**)&pS1, g_S1);
    cudaGetSymbolAddress((void**)&pS2, g_S2);
    cudaGetSymbolAddress((void**)&pA,  g_A);
    cudaGetSymbolAddress((void**)&pC,  g_C);
    cudaGetSymbolAddress((void**)&pE2, g_E2);
    cudaGetSymbolAddress((void**)&pGE, g_GE);
    cudaGetSymbolAddress((void**)&pV1, g_V1);
    cudaGetSymbolAddress((void**)&pV2, g_V2);
    cudaGetSymbolAddress((void**)&pV3, g_V3);
    cudaGetSymbolAddress((void**)&pc1, g_c1);
    cudaGetSymbolAddress((void**)&pdeg, g_deg);
    cudaGetSymbolAddress((void**)&peoff, g_eoff);
    cudaGetSymbolAddress((void**)&peidx, g_eidx);
    cudaGetSymbolAddress((void**)&pnoff, g_noff);
    cudaGetSymbolAddress((void**)&pnidx, g_nidx);
    cudaGetSymbolAddress((void**)&pvoff, g_voff);
    cudaGetSymbolAddress((void**)&pvidx, g_vidx);
    cudaGetSymbolAddress((void**)&pmoff, g_moff);
    cudaGetSymbolAddress((void**)&pmidx, g_midx);
    cudaGetSymbolAddress((void**)&pvval, g_vval);
    cudaGetSymbolAddress((void**)&pmval, g_mval);

    size_t smem128 = (size_t)(128 * 132 + 128 * 68) * sizeof(float);
    size_t smem256 = (size_t)(256 * 132 + 256 * 68) * sizeof(float);
    cudaFuncSetAttribute(gemm_tiled_kernel<128, false>,
                         cudaFuncAttributeMaxDynamicSharedMemorySize, (int)smem128);
    cudaFuncSetAttribute(gemm_tiled_kernel<256, true>,
                         cudaFuncAttributeMaxDynamicSharedMemorySize, (int)smem256);

    const int BLK = 256;
    int ew = (N_HEDGES + 7) / 8;
    int nw = (N_NODES + 7) / 8;
    int gemmN = (N_NODES + GEMM_RT - 1) / GEMM_RT;
    int gemmE = (N_HEDGES + GEMM_RT - 1) / GEMM_RT;
    int one_per_thread = (NNZ_INC + BLK - 1) / BLK;

    // --- CSR build ---
    zero_cnt_kernel<<<256, 256>>>();
    hist_kernel<<<one_per_thread, BLK>>>(inc_src, inc_dst, vmat_rows, emat_rows);
    scan4_kernel<<<4, 1024>>>();
    fill_kernel<<<one_per_thread, BLK>>>(inc_src, inc_dst, vmat_rows, vmat_cols, vmat_vals,
                                         emat_rows, emat_cols, emat_vals);

    // --- pass 1 ---
    edge_gather1_kernel<<<ew, BLK>>>(vfeat, invDV);                          // S1, c1, deg
    gemm_tiled_kernel<256, true><<<gemmE, 256, smem256>>>(
        pS1, efeat, pc1, nullptr, nullptr, psi1_W, psi1_b, pA, N_HEDGES, 0); // A
    gather_wsum_kernel<<<ew, BLK>>>(pmoff, pmidx, pmval, pA, pC, N_HEDGES);  // C = emat@A
    gather_dual_kernel<<<nw, BLK>>>(pnoff, pnidx, efeat, pC, pV2, pV1,
                                    N_NODES, 1);                             // V2, V1=V2+ΣC
    gemm_tiled_kernel<128, false><<<gemmN, 256, smem128>>>(
        pV1, nullptr, nullptr, nullptr, nullptr, Wv, nullptr, vout, N_NODES, 1); // vout

    // --- pass 2 ---
    gather_wsum_kernel<<<nw, BLK>>>(pvoff, pvidx, pvval, pV2, pV3, N_NODES); // V3 = vmat@V2
    gather_dual_kernel<<<ew, BLK>>>(peoff, peidx, vout, pV3, pS2, pGE,
                                    N_HEDGES, 0);                            // S2, GE
    gemm_tiled_kernel<256, true><<<gemmE, 256, smem256>>>(
        pS2, efeat, pdeg, invDE, pGE, psi2_W, psi2_b, pE2, N_HEDGES, 0);     // E2 = B*invDE + GE
    gemm_tiled_kernel<128, false><<<gemmE, 256, smem128>>>(
        pE2, nullptr, nullptr, nullptr, nullptr, We, nullptr, eout, N_HEDGES, 1); // eout
}

// round 7
// speedup vs baseline: 2.3217x; 1.0868x over previous
#include <cuda_runtime.h>
#include <cstdint>

#define N_NODES 50000
#define N_HEDGES 10000
#define NNZ_INC 400000
#define NNZ_E 80000
#define NNZ_V 400000
#define D 128

// ---------------- scratch ----------------
__device__ float g_S1[(size_t)N_HEDGES * D];
__device__ float g_S2[(size_t)N_HEDGES * D];
__device__ float g_A [(size_t)N_HEDGES * D];
__device__ float g_C [(size_t)N_HEDGES * D];
__device__ float g_E2[(size_t)N_HEDGES * D];
__device__ float g_GE[(size_t)N_HEDGES * D];
__device__ float g_V1[(size_t)N_NODES * D];
__device__ float g_V2[(size_t)N_NODES * D];
__device__ float g_V3[(size_t)N_NODES * D];
__device__ float g_c1[N_HEDGES];
__device__ float g_deg[N_HEDGES];

// CSR scratch
__device__ int g_ecnt[N_HEDGES];  __device__ int g_eoff[N_HEDGES + 1];  __device__ int g_ecur[N_HEDGES];
__device__ int g_ncnt[N_NODES];   __device__ int g_noff[N_NODES + 1];   __device__ int g_ncur[N_NODES];
__device__ int g_vcnt[N_NODES];   __device__ int g_voff[N_NODES + 1];   __device__ int g_vcur[N_NODES];
__device__ int g_mcnt[N_HEDGES];  __device__ int g_moff[N_HEDGES + 1];  __device__ int g_mcur[N_HEDGES];
__device__ int   g_eidx[NNZ_INC];
__device__ int   g_nidx[NNZ_INC];
__device__ int   g_vidx[NNZ_V];
__device__ float g_vval[NNZ_V];
__device__ int   g_midx[NNZ_E];
__device__ float g_mval[NNZ_E];

// ---------------- helpers ----------------
__device__ __forceinline__ double ffma2(double a, double b, double c) {
    double d;
    asm("fma.rn.f32x2 %0, %1, %2, %3;" : "=d"(d) : "d"(a), "d"(b), "d"(c));
    return d;
}
__device__ __forceinline__ double dup2(float v) {
    double d;
    asm("mov.b64 %0, {%1, %1};" : "=d"(d) : "f"(v));
    return d;
}
__device__ __forceinline__ float2 unpk(double d) {
    float2 r;
    asm("mov.b64 {%0, %1}, %2;" : "=f"(r.x), "=f"(r.y) : "d"(d));
    return r;
}
__device__ __forceinline__ void acc4(float4& a, float4 v) {
    a.x += v.x; a.y += v.y; a.z += v.z; a.w += v.w;
}
__device__ __forceinline__ void facc4(float4& a, float s, float4 v) {
    a.x = fmaf(s, v.x, a.x); a.y = fmaf(s, v.y, a.y);
    a.z = fmaf(s, v.z, a.z); a.w = fmaf(s, v.w, a.w);
}

// ---------------- CSR build (split E vs NVM) ----------------
__global__ void zeroE_kernel() {
    int i = blockIdx.x * blockDim.x + threadIdx.x;
    if (i < N_HEDGES) g_ecnt[i] = 0;
}
__global__ void zeroNVM_kernel() {
    int i = blockIdx.x * blockDim.x + threadIdx.x;
    int stride = gridDim.x * blockDim.x;
    for (int k = i; k < N_NODES; k += stride) { g_ncnt[k] = 0; g_vcnt[k] = 0; }
    for (int k = i; k < N_HEDGES; k += stride) g_mcnt[k] = 0;
}

__global__ void histE_kernel(const int* __restrict__ dst) {
    int k = blockIdx.x * blockDim.x + threadIdx.x;
    if (k < NNZ_INC) atomicAdd(&g_ecnt[__ldg(dst + k)], 1);
}
__global__ void histNVM_kernel(const int* __restrict__ src,
                               const int* __restrict__ vrows,
                               const int* __restrict__ mrows) {
    int k = blockIdx.x * blockDim.x + threadIdx.x;
    if (k < NNZ_INC) {
        atomicAdd(&g_ncnt[__ldg(src + k)], 1);
        atomicAdd(&g_vcnt[__ldg(vrows + k)], 1);
        if (k < NNZ_E) atomicAdd(&g_mcnt[__ldg(mrows + k)], 1);
    }
}

__device__ void scan_one(const int* cnt, int* off, int* cur, int n) {
    __shared__ int ssum[1024];
    int t = threadIdx.x;
    int chunk = (n + 1023) >> 10;
    int b = t * chunk;
    int e = min(b + chunk, n);
    int s = 0;
    for (int i = b; i < e; i++) s += cnt[i];
    ssum[t] = s;
    __syncthreads();
    for (int d = 1; d < 1024; d <<= 1) {
        int v = (t >= d) ? ssum[t - d] : 0;
        __syncthreads();
        ssum[t] += v;
        __syncthreads();
    }
    int ex = (t == 0) ? 0 : ssum[t - 1];
    for (int i = b; i < e; i++) { off[i] = ex; cur[i] = ex; ex += cnt[i]; }
    if (t == 1023) off[n] = ssum[1023];
}
__global__ void scanE_kernel() { scan_one(g_ecnt, g_eoff, g_ecur, N_HEDGES); }
__global__ void scanNVM_kernel() {
    if (blockIdx.x == 0)      scan_one(g_ncnt, g_noff, g_ncur, N_NODES);
    else if (blockIdx.x == 1) scan_one(g_vcnt, g_voff, g_vcur, N_NODES);
    else                      scan_one(g_mcnt, g_moff, g_mcur, N_HEDGES);
}

__global__ void fillE_kernel(const int* __restrict__ src, const int* __restrict__ dst) {
    int k = blockIdx.x * blockDim.x + threadIdx.x;
    if (k >= NNZ_INC) return;
    int d = __ldg(dst + k);
    int pe = atomicAdd(&g_ecur[d], 1);
    g_eidx[pe] = __ldg(src + k);
}
__global__ void fillNVM_kernel(const int* __restrict__ src, const int* __restrict__ dst,
                               const int* __restrict__ vrows, const int* __restrict__ vcols,
                               const float* __restrict__ vvals,
                               const int* __restrict__ mrows, const int* __restrict__ mcols,
                               const float* __restrict__ mvals) {
    int k = blockIdx.x * blockDim.x + threadIdx.x;
    if (k >= NNZ_INC) return;
    int s = __ldg(src + k), r = __ldg(vrows + k);
    int pn = atomicAdd(&g_ncur[s], 1);
    g_nidx[pn] = __ldg(dst + k);
    int pv = atomicAdd(&g_vcur[r], 1);
    g_vidx[pv] = __ldg(vcols + k);
    g_vval[pv] = __ldg(vvals + k);
    if (k < NNZ_E) {
        int mr = __ldg(mrows + k);
        int pm = atomicAdd(&g_mcur[mr], 1);
        g_midx[pm] = __ldg(mcols + k);
        g_mval[pm] = __ldg(mvals + k);
    }
}

// ---------------- gather kernels (warp per row, unroll 4) ----------------
__global__ void edge_gather1_kernel(const float* __restrict__ vfeat,
                                    const float* __restrict__ invDV) {
    int w = (blockIdx.x * blockDim.x + threadIdx.x) >> 5;
    int lane = threadIdx.x & 31;
    if (w >= N_HEDGES) return;
    int b = g_eoff[w], e = g_eoff[w + 1];
    float4 a0 = make_float4(0.f,0.f,0.f,0.f), a1 = a0, a2 = a0, a3 = a0;
    float c0 = 0.f, c1s = 0.f, c2s = 0.f, c3s = 0.f;
    int j = b;
    for (; j + 4 <= e; j += 4) {
        int s0 = g_eidx[j], s1 = g_eidx[j+1], s2 = g_eidx[j+2], s3 = g_eidx[j+3];
        float i0 = invDV[s0], i1 = invDV[s1], i2 = invDV[s2], i3 = invDV[s3];
        float4 v0 = *(const float4*)(vfeat + (size_t)s0 * D + lane * 4);
        float4 v1 = *(const float4*)(vfeat + (size_t)s1 * D + lane * 4);
        float4 v2 = *(const float4*)(vfeat + (size_t)s2 * D + lane * 4);
        float4 v3 = *(const float4*)(vfeat + (size_t)s3 * D + lane * 4);
        facc4(a0, i0, v0); facc4(a1, i1, v1); facc4(a2, i2, v2); facc4(a3, i3, v3);
        c0 += i0; c1s += i1; c2s += i2; c3s += i3;
    }
    for (; j < e; j++) {
        int s0 = g_eidx[j];
        float i0 = invDV[s0];
        float4 v0 = *(const float4*)(vfeat + (size_t)s0 * D + lane * 4);
        facc4(a0, i0, v0);
        c0 += i0;
    }
    a0.x += a1.x + a2.x + a3.x; a0.y += a1.y + a2.y + a3.y;
    a0.z += a1.z + a2.z + a3.z; a0.w += a1.w + a2.w + a3.w;
    *(float4*)(g_S1 + (size_t)w * D + lane * 4) = a0;
    if (lane == 0) { g_c1[w] = c0 + c1s + c2s + c3s; g_deg[w] = (float)(e - b); }
}

// Y[r] = (base ? base[r] : 0) + sum X[idx[j]]
__global__ void gather_sum_kernel(const int* __restrict__ off, const int* __restrict__ idx,
                                  const float* __restrict__ X, const float* __restrict__ base,
                                  float* __restrict__ Y, int R) {
    int w = (blockIdx.x * blockDim.x + threadIdx.x) >> 5;
    int lane = threadIdx.x & 31;
    if (w >= R) return;
    int b = off[w], e = off[w + 1];
    float4 a0 = make_float4(0.f,0.f,0.f,0.f), a1 = a0, a2 = a0, a3 = a0;
    int j = b;
    for (; j + 4 <= e; j += 4) {
        int s0 = idx[j], s1 = idx[j+1], s2 = idx[j+2], s3 = idx[j+3];
        float4 v0 = *(const float4*)(X + (size_t)s0 * D + lane * 4);
        float4 v1 = *(const float4*)(X + (size_t)s1 * D + lane * 4);
        float4 v2 = *(const float4*)(X + (size_t)s2 * D + lane * 4);
        float4 v3 = *(const float4*)(X + (size_t)s3 * D + lane * 4);
        acc4(a0, v0); acc4(a1, v1); acc4(a2, v2); acc4(a3, v3);
    }
    for (; j < e; j++) {
        float4 v0 = *(const float4*)(X + (size_t)idx[j] * D + lane * 4);
        acc4(a0, v0);
    }
    a0.x += a1.x + a2.x + a3.x; a0.y += a1.y + a2.y + a3.y;
    a0.z += a1.z + a2.z + a3.z; a0.w += a1.w + a2.w + a3.w;
    if (base) {
        float4 bs = *(const float4*)(base + (size_t)w * D + lane * 4);
        acc4(a0, bs);
    }
    *(float4*)(Y + (size_t)w * D + lane * 4) = a0;
}

// Dual gather: YA[r] = sum XA[idx[j]], YB[r] = sum XB[idx[j]]
__global__ void gather_dual_kernel(const int* __restrict__ off, const int* __restrict__ idx,
                                   const float* __restrict__ XA, const float* __restrict__ XB,
                                   float* __restrict__ YA, float* __restrict__ YB, int R) {
    int w = (blockIdx.x * blockDim.x + threadIdx.x) >> 5;
    int lane = threadIdx.x & 31;
    if (w >= R) return;
    int b = off[w], e = off[w + 1];
    float4 aa0 = make_float4(0.f,0.f,0.f,0.f), aa1 = aa0, ab0 = aa0, ab1 = aa0;
    int j = b;
    for (; j + 2 <= e; j += 2) {
        int s0 = idx[j], s1 = idx[j+1];
        float4 va0 = *(const float4*)(XA + (size_t)s0 * D + lane * 4);
        float4 vb0 = *(const float4*)(XB + (size_t)s0 * D + lane * 4);
        float4 va1 = *(const float4*)(XA + (size_t)s1 * D + lane * 4);
        float4 vb1 = *(const float4*)(XB + (size_t)s1 * D + lane * 4);
        acc4(aa0, va0); acc4(ab0, vb0); acc4(aa1, va1); acc4(ab1, vb1);
    }
    for (; j < e; j++) {
        int s0 = idx[j];
        float4 va0 = *(const float4*)(XA + (size_t)s0 * D + lane * 4);
        float4 vb0 = *(const float4*)(XB + (size_t)s0 * D + lane * 4);
        acc4(aa0, va0); acc4(ab0, vb0);
    }
    aa0.x += aa1.x; aa0.y += aa1.y; aa0.z += aa1.z; aa0.w += aa1.w;
    ab0.x += ab1.x; ab0.y += ab1.y; ab0.z += ab1.z; ab0.w += ab1.w;
    *(float4*)(YA + (size_t)w * D + lane * 4) = aa0;
    *(float4*)(YB + (size_t)w * D + lane * 4) = ab0;
}

// Y[r] = sum wv[j] * X[idx[j]]
__global__ void gather_wsum_kernel(const int* __restrict__ off, const int* __restrict__ idx,
                                   const float* __restrict__ wv, const float* __restrict__ X,
                                   float* __restrict__ Y, int R) {
    int w = (blockIdx.x * blockDim.x + threadIdx.x) >> 5;
    int lane = threadIdx.x & 31;
    if (w >= R) return;
    int b = off[w], e = off[w + 1];
    float4 a0 = make_float4(0.f,0.f,0.f,0.f), a1 = a0, a2 = a0, a3 = a0;
    int j = b;
    for (; j + 4 <= e; j += 4) {
        int s0 = idx[j], s1 = idx[j+1], s2 = idx[j+2], s3 = idx[j+3];
        float w0 = wv[j], w1 = wv[j+1], w2 = wv[j+2], w3 = wv[j+3];
        float4 v0 = *(const float4*)(X + (size_t)s0 * D + lane * 4);
        float4 v1 = *(const float4*)(X + (size_t)s1 * D + lane * 4);
        float4 v2 = *(const float4*)(X + (size_t)s2 * D + lane * 4);
        float4 v3 = *(const float4*)(X + (size_t)s3 * D + lane * 4);
        facc4(a0, w0, v0); facc4(a1, w1, v1); facc4(a2, w2, v2); facc4(a3, w3, v3);
    }
    for (; j < e; j++) {
        float w0 = wv[j];
        float4 v0 = *(const float4*)(X + (size_t)idx[j] * D + lane * 4);
        facc4(a0, w0, v0);
    }
    a0.x += a1.x + a2.x + a3.x; a0.y += a1.y + a2.y + a3.y;
    a0.z += a1.z + a2.z + a3.z; a0.w += a1.w + a2.w + a3.w;
    *(float4*)(Y + (size_t)w * D + lane * 4) = a0;
}

// ---------------- tiled GEMM ----------------
// Y = act( ([X | coef*ef] @ W^T + coef*b) * oscale + addend )
#define GEMM_RT 64
template <int K, bool CONCAT>
__global__ void gemm_tiled_kernel(const float* __restrict__ X, const float* __restrict__ ef,
                                  const float* __restrict__ coef, const float* __restrict__ oscale,
                                  const float* __restrict__ addend,
                                  const float* __restrict__ W, const float* __restrict__ bias,
                                  float* __restrict__ Y, int R, int do_relu) {
    extern __shared__ float sh[];
    float* sWt = sh;               // [K][132]
    float* sXt = sh + K * 132;     // [K][68]
    const int tid = threadIdx.x;
    const int tc = tid & 31;
    const int tr = tid >> 5;
    const int row0 = blockIdx.x * GEMM_RT;

    for (int idx = tid; idx < 128 * K; idx += 256) {
        int col = idx / K, k = idx - col * K;
        sWt[k * 132 + col] = W[idx];
    }
    constexpr int NQ = K / 4;
    for (int idx = tid; idx < GEMM_RT * NQ; idx += 256) {
        int row = idx / NQ, kq = idx - row * NQ;
        int kk = kq * 4;
        int gr = row0 + row;
        float4 val = make_float4(0.f, 0.f, 0.f, 0.f);
        if (gr < R) {
            if (!CONCAT || kk < 128) {
                val = *(const float4*)(X + (size_t)gr * 128 + kk);
            } else {
                float cf = coef[gr];
                float4 ev = *(const float4*)(ef + (size_t)gr * 128 + (kk - 128));
                val.x = cf * ev.x; val.y = cf * ev.y; val.z = cf * ev.z; val.w = cf * ev.w;
            }
        }
        float* dstp = sXt + (size_t)kk * 68 + row;
        dstp[0]   = val.x;
        dstp[68]  = val.y;
        dstp[136] = val.z;
        dstp[204] = val.w;
    }
    __syncthreads();

    double acc[4][4];
#pragma unroll
    for (int p = 0; p < 4; p++)
#pragma unroll
        for (int c = 0; c < 4; c++) acc[p][c] = 0.0;

    const int c0 = tc * 4;
    const int r0 = tr * 8;
#pragma unroll 8
    for (int k = 0; k < K; k++) {
        float4 wv = *(const float4*)(sWt + k * 132 + c0);
        double2 xd01 = *(const double2*)(sXt + k * 68 + r0);
        double2 xd23 = *(const double2*)(sXt + k * 68 + r0 + 4);
        double w0 = dup2(wv.x), w1 = dup2(wv.y), w2 = dup2(wv.z), w3 = dup2(wv.w);
        acc[0][0] = ffma2(xd01.x, w0, acc[0][0]);
        acc[0][1] = ffma2(xd01.x, w1, acc[0][1]);
        acc[0][2] = ffma2(xd01.x, w2, acc[0][2]);
        acc[0][3] = ffma2(xd01.x, w3, acc[0][3]);
        acc[1][0] = ffma2(xd01.y, w0, acc[1][0]);
        acc[1][1] = ffma2(xd01.y, w1, acc[1][1]);
        acc[1][2] = ffma2(xd01.y, w2, acc[1][2]);
        acc[1][3] = ffma2(xd01.y, w3, acc[1][3]);
        acc[2][0] = ffma2(xd23.x, w0, acc[2][0]);
        acc[2][1] = ffma2(xd23.x, w1, acc[2][1]);
        acc[2][2] = ffma2(xd23.x, w2, acc[2][2]);
        acc[2][3] = ffma2(xd23.x, w3, acc[2][3]);
        acc[3][0] = ffma2(xd23.y, w0, acc[3][0]);
        acc[3][1] = ffma2(xd23.y, w1, acc[3][1]);
        acc[3][2] = ffma2(xd23.y, w2, acc[3][2]);
        acc[3][3] = ffma2(xd23.y, w3, acc[3][3]);
    }

    float4 bv = make_float4(0.f, 0.f, 0.f, 0.f);
    if (bias) bv = *(const float4*)(bias + c0);
    int row_base = row0 + r0;
#pragma unroll
    for (int p = 0; p < 4; p++) {
        float2 y0 = unpk(acc[p][0]);
        float2 y1 = unpk(acc[p][1]);
        float2 y2 = unpk(acc[p][2]);
        float2 y3 = unpk(acc[p][3]);
#pragma unroll
        for (int h = 0; h < 2; h++) {
            int row = row_base + 2 * p + h;
            if (row >= R) continue;
            float4 o = (h == 0) ? make_float4(y0.x, y1.x, y2.x, y3.x)
                                : make_float4(y0.y, y1.y, y2.y, y3.y);
            if (bias) {
                float cf = coef ? coef[row] : 1.f;
                o.x = fmaf(cf, bv.x, o.x); o.y = fmaf(cf, bv.y, o.y);
                o.z = fmaf(cf, bv.z, o.z); o.w = fmaf(cf, bv.w, o.w);
            }
            if (oscale) {
                float os = oscale[row];
                o.x *= os; o.y *= os; o.z *= os; o.w *= os;
            }
            if (addend) {
                float4 ad = *(const float4*)(addend + (size_t)row * 128 + c0);
                o.x += ad.x; o.y += ad.y; o.z += ad.z; o.w += ad.w;
            }
            if (do_relu) {
                o.x = fmaxf(o.x, 0.f); o.y = fmaxf(o.y, 0.f);
                o.z = fmaxf(o.z, 0.f); o.w = fmaxf(o.w, 0.f);
            }
            *(float4*)(Y + (size_t)row * 128 + c0) = o;
        }
    }
}

// ---------------- launch ----------------
extern "C" void kernel_launch(void* const* d_in, const int* in_sizes, int n_in,
                              void* d_out, int out_size) {
    const float* vfeat    = (const float*)d_in[0];
    const float* efeat    = (const float*)d_in[1];
    const float* invDV    = (const float*)d_in[2];
    const float* invDE    = (const float*)d_in[3];
    const int*   inc_src  = (const int*)d_in[4];
    const int*   inc_dst  = (const int*)d_in[5];
    const int*   emat_rows = (const int*)d_in[6];
    const int*   emat_cols = (const int*)d_in[7];
    const float* emat_vals = (const float*)d_in[8];
    const int*   vmat_rows = (const int*)d_in[9];
    const int*   vmat_cols = (const int*)d_in[10];
    const float* vmat_vals = (const float*)d_in[11];
    const float* Wv      = (const float*)d_in[12];
    const float* We      = (const float*)d_in[13];
    const float* psi1_W  = (const float*)d_in[14];
    const float* psi1_b  = (const float*)d_in[15];
    const float* psi2_W  = (const float*)d_in[16];
    const float* psi2_b  = (const float*)d_in[17];

    float* out  = (float*)d_out;
    float* vout = out;
    float* eout = out + (size_t)N_NODES * D;

    float *pS1, *pS2, *pA, *pC, *pE2, *pGE, *pV1, *pV2, *pV3, *pc1, *pdeg;
    int *peoff, *peidx, *pnoff, *pnidx, *pvoff, *pvidx, *pmoff, *pmidx;
    float *pvval, *pmval;
    cudaGetSymbolAddress((void**)&pS1, g_S1);
    cudaGetSymbolAddress((void**)&pS2, g_S2);
    cudaGetSymbolAddress((void**)&pA,  g_A);
    cudaGetSymbolAddress((void**)&pC,  g_C);
    cudaGetSymbolAddress((void**)&pE2, g_E2);
    cudaGetSymbolAddress((void**)&pGE, g_GE);
    cudaGetSymbolAddress((void**)&pV1, g_V1);
    cudaGetSymbolAddress((void**)&pV2, g_V2);
    cudaGetSymbolAddress((void**)&pV3, g_V3);
    cudaGetSymbolAddress((void**)&pc1, g_c1);
    cudaGetSymbolAddress((void**)&pdeg, g_deg);
    cudaGetSymbolAddress((void**)&peoff, g_eoff);
    cudaGetSymbolAddress((void**)&peidx, g_eidx);
    cudaGetSymbolAddress((void**)&pnoff, g_noff);
    cudaGetSymbolAddress((void**)&pnidx, g_nidx);
    cudaGetSymbolAddress((void**)&pvoff, g_voff);
    cudaGetSymbolAddress((void**)&pvidx, g_vidx);
    cudaGetSymbolAddress((void**)&pmoff, g_moff);
    cudaGetSymbolAddress((void**)&pmidx, g_midx);
    cudaGetSymbolAddress((void**)&pvval, g_vval);
    cudaGetSymbolAddress((void**)&pmval, g_mval);

    size_t smem128 = (size_t)(128 * 132 + 128 * 68) * sizeof(float);
    size_t smem256 = (size_t)(256 * 132 + 256 * 68) * sizeof(float);
    cudaFuncSetAttribute(gemm_tiled_kernel<128, false>,
                         cudaFuncAttributeMaxDynamicSharedMemorySize, (int)smem128);
    cudaFuncSetAttribute(gemm_tiled_kernel<256, true>,
                         cudaFuncAttributeMaxDynamicSharedMemorySize, (int)smem256);

    // --- streams + events (host infra; created once, identical work every call) ---
    static cudaStream_t s1 = nullptr;
    static cudaEvent_t evRoot = nullptr, evM = nullptr, evV2 = nullptr, evB = nullptr;
    if (s1 == nullptr) {
        cudaStreamCreateWithFlags(&s1, cudaStreamNonBlocking);
        cudaEventCreateWithFlags(&evRoot, cudaEventDisableTiming);
        cudaEventCreateWithFlags(&evM,    cudaEventDisableTiming);
        cudaEventCreateWithFlags(&evV2,   cudaEventDisableTiming);
        cudaEventCreateWithFlags(&evB,    cudaEventDisableTiming);
    }

    const int BLK = 256;
    int ew = (N_HEDGES + 7) / 8;
    int nw = (N_NODES + 7) / 8;
    int gemmN = (N_NODES + GEMM_RT - 1) / GEMM_RT;
    int gemmE = (N_HEDGES + GEMM_RT - 1) / GEMM_RT;
    int nnz_blk = (NNZ_INC + BLK - 1) / BLK;

    // fork: stream B (s1) handles n/v/m CSR + V2 + V3
    cudaEventRecord(evRoot, 0);
    cudaStreamWaitEvent(s1, evRoot, 0);

    // --- stream B chain ---
    zeroNVM_kernel<<<256, 256, 0, s1>>>();
    histNVM_kernel<<<nnz_blk, BLK, 0, s1>>>(inc_src, vmat_rows, emat_rows);
    scanNVM_kernel<<<3, 1024, 0, s1>>>();
    fillNVM_kernel<<<nnz_blk, BLK, 0, s1>>>(inc_src, inc_dst, vmat_rows, vmat_cols, vmat_vals,
                                            emat_rows, emat_cols, emat_vals);
    cudaEventRecord(evM, s1);                                            // n,m CSR ready
    gather_sum_kernel<<<nw, BLK, 0, s1>>>(pnoff, pnidx, efeat, nullptr, pV2, N_NODES); // V2
    cudaEventRecord(evV2, s1);
    gather_wsum_kernel<<<nw, BLK, 0, s1>>>(pvoff, pvidx, pvval, pV2, pV3, N_NODES);    // V3
    cudaEventRecord(evB, s1);

    // --- stream A (legacy) critical chain ---
    zeroE_kernel<<<(N_HEDGES + 255) / 256, 256>>>();
    histE_kernel<<<nnz_blk, BLK>>>(inc_dst);
    scanE_kernel<<<1, 1024>>>();
    fillE_kernel<<<nnz_blk, BLK>>>(inc_src, inc_dst);
    edge_gather1_kernel<<<ew, BLK>>>(vfeat, invDV);                      // S1, c1, deg
    gemm_tiled_kernel<256, true><<<gemmE, 256, smem256>>>(
        pS1, efeat, pc1, nullptr, nullptr, psi1_W, psi1_b, pA, N_HEDGES, 0);  // A
    cudaStreamWaitEvent(0, evM, 0);
    gather_wsum_kernel<<<ew, BLK>>>(pmoff, pmidx, pmval, pA, pC, N_HEDGES);   // C = emat@A
    cudaStreamWaitEvent(0, evV2, 0);
    gather_sum_kernel<<<nw, BLK>>>(pnoff, pnidx, pC, pV2, pV1, N_NODES);      // V1 = V2 + ΣC
    gemm_tiled_kernel<128, false><<<gemmN, 256, smem128>>>(
        pV1, nullptr, nullptr, nullptr, nullptr, Wv, nullptr, vout, N_NODES, 1); // vout
    cudaStreamWaitEvent(0, evB, 0);
    gather_dual_kernel<<<ew, BLK>>>(peoff, peidx, vout, pV3, pS2, pGE, N_HEDGES); // S2, GE
    gemm_tiled_kernel<256, true><<<gemmE, 256, smem256>>>(
        pS2, efeat, pdeg, invDE, pGE, psi2_W, psi2_b, pE2, N_HEDGES, 0);      // E2
    gemm_tiled_kernel<128, false><<<gemmE, 256, smem128>>>(
        pE2, nullptr, nullptr, nullptr, nullptr, We, nullptr, eout, N_HEDGES, 1); // eout
}